// round 14
// baseline (speedup 1.0000x reference)
#include <cuda_runtime.h>
#include <stdint.h>

// Problem shapes (fixed by the dataset)
#define B 32
#define T 8192
#define D 128
#define P 1024
#define THREADS 128   // 4 warps/block — measured optimum of the granularity axis

// Per-phoneme start frame (exclusive prefix of durations).
__device__ int g_start[B * P];

// ---------------------------------------------------------------------------
// Kernel 1: scan. 32 blocks x 256 threads; thread t owns durations [4t,4t+4)
// of its batch. shfl warp scan + cross-warp pass, writes starts (int4).
// ---------------------------------------------------------------------------
__global__ void __launch_bounds__(256) scan_kernel(const int* __restrict__ dur) {
    __shared__ int s_wsum[8];
    const int b    = blockIdx.x;
    const int t    = threadIdx.x;
    const int lane = t & 31;
    const int wid  = t >> 5;

    const int4 dv = reinterpret_cast<const int4*>(dur + b * P)[t];
    const int tsum = dv.x + dv.y + dv.z + dv.w;

    int x = tsum;
    #pragma unroll
    for (int off = 1; off < 32; off <<= 1) {
        int y = __shfl_up_sync(0xFFFFFFFFu, x, off);
        if (lane >= off) x += y;
    }
    if (lane == 31) s_wsum[wid] = x;
    __syncthreads();

    if (wid == 0) {
        int s  = (lane < 8) ? s_wsum[lane] : 0;
        int tt = s;
        #pragma unroll
        for (int off = 1; off < 8; off <<= 1) {
            int y = __shfl_up_sync(0xFFFFFFFFu, tt, off);
            if (lane >= off) tt += y;
        }
        if (lane < 8) s_wsum[lane] = tt - s;
    }
    __syncthreads();

    int st = s_wsum[wid] + x - tsum;         // exclusive prefix before 4t
    int4 pk;
    pk.x = st;  st += dv.x;
    pk.y = st;  st += dv.y;
    pk.z = st;  st += dv.z;
    pk.w = st;
    reinterpret_cast<int4*>(g_start + b * P)[t] = pk;
}

// ---------------------------------------------------------------------------
// Kernel 2: pure gather, PDL-launched. Grid 8192 x 128 threads (4 warps):
// one phoneme per warp. The duration is a pure input, so it is loaded BEFORE
// the PDL sync (overlapping its latency with the wait); only the scan-
// produced start is read after release. 8 predicated __ldcs LDG.128 +
// 1 STG.128 per warp.
// ---------------------------------------------------------------------------
__global__ void __launch_bounds__(THREADS) avg_kernel(
    const float* __restrict__ mel,
    const int*   __restrict__ dur,
    float*       __restrict__ out)
{
    const int wid  = threadIdx.x >> 5;
    const int lane = threadIdx.x & 31;
    const int gp   = blockIdx.x * 4 + wid;   // global phoneme index
    const int b    = gp >> 10;               // / P
    const int p    = gp & (P - 1);           // % P

    // Duration load issues before the PDL wait (input, not scan-produced).
    const int d = dur[b * P + p];

    // Wait for scan kernel's writes to be visible (PDL release).
    cudaGridDependencySynchronize();

    const int st = g_start[b * P + p];

    const float4* __restrict__ base =
        reinterpret_cast<const float4*>(mel + ((size_t)b * T + st) * D) + lane;

    float4 acc = make_float4(0.f, 0.f, 0.f, 0.f);
    #pragma unroll
    for (int f = 0; f < 8; ++f) {
        if (f < d) {
            float4 v = __ldcs(base + f * (D / 4));
            acc.x += v.x; acc.y += v.y; acc.z += v.z; acc.w += v.w;
        }
    }

    const float inv = (d > 0) ? (1.0f / (float)d) : 0.0f;
    acc.x *= inv; acc.y *= inv; acc.z *= inv; acc.w *= inv;

    __stcs(reinterpret_cast<float4*>(out + ((size_t)b * P + p) * D) + lane, acc);
}

extern "C" void kernel_launch(void* const* d_in, const int* in_sizes, int n_in,
                              void* d_out, int out_size) {
    const float* mel = (const float*)d_in[0];
    const int*   dur = (const int*)d_in[1];
    float*       out = (float*)d_out;

    scan_kernel<<<B, 256>>>(dur);

    cudaLaunchConfig_t cfg = {};
    cfg.gridDim  = dim3((B * P) / 4, 1, 1);
    cfg.blockDim = dim3(THREADS, 1, 1);
    cudaLaunchAttribute attrs[1];
    attrs[0].id = cudaLaunchAttributeProgrammaticStreamSerialization;
    attrs[0].val.programmaticStreamSerializationAllowed = 1;
    cfg.attrs    = attrs;
    cfg.numAttrs = 1;
    cudaLaunchKernelEx(&cfg, avg_kernel, mel, dur, out);
}

// round 15
// speedup vs baseline: 1.1295x; 1.1295x over previous
#include <cuda_runtime.h>
#include <stdint.h>

// Problem shapes (fixed by the dataset)
#define B 32
#define T 8192
#define D 128
#define P 1024
#define THREADS 128   // 4 warps/block — measured optimum of the granularity axis

// Packed per-phoneme segment: (start << 4) | duration   (start < 8192, d <= 8)
__device__ int g_seg[B * P];

// ---------------------------------------------------------------------------
// Kernel 1: scan. 32 blocks x 256 threads; thread t owns durations [4t,4t+4)
// of its batch. shfl warp scan + cross-warp pass, writes packed segs (int4).
// ---------------------------------------------------------------------------
__global__ void __launch_bounds__(256) scan_kernel(const int* __restrict__ dur) {
    __shared__ int s_wsum[8];
    const int b    = blockIdx.x;
    const int t    = threadIdx.x;
    const int lane = t & 31;
    const int wid  = t >> 5;

    const int4 dv = reinterpret_cast<const int4*>(dur + b * P)[t];
    const int tsum = dv.x + dv.y + dv.z + dv.w;

    int x = tsum;
    #pragma unroll
    for (int off = 1; off < 32; off <<= 1) {
        int y = __shfl_up_sync(0xFFFFFFFFu, x, off);
        if (lane >= off) x += y;
    }
    if (lane == 31) s_wsum[wid] = x;
    __syncthreads();

    if (wid == 0) {
        int s  = (lane < 8) ? s_wsum[lane] : 0;
        int tt = s;
        #pragma unroll
        for (int off = 1; off < 8; off <<= 1) {
            int y = __shfl_up_sync(0xFFFFFFFFu, tt, off);
            if (lane >= off) tt += y;
        }
        if (lane < 8) s_wsum[lane] = tt - s;
    }
    __syncthreads();

    int st = s_wsum[wid] + x - tsum;         // exclusive prefix before 4t
    int4 pk;
    pk.x = (st << 4) | dv.x;  st += dv.x;
    pk.y = (st << 4) | dv.y;  st += dv.y;
    pk.z = (st << 4) | dv.z;  st += dv.z;
    pk.w = (st << 4) | dv.w;
    reinterpret_cast<int4*>(g_seg + b * P)[t] = pk;
}

// ---------------------------------------------------------------------------
// Kernel 2: pure gather, PDL-launched. Grid 8192 x 128 threads (4 warps):
// one phoneme per warp. Nothing but index math before the PDL sync; one
// packed g_seg read after release, then 8 predicated __ldcs LDG.128 +
// 1 STG.128 per warp.
// ---------------------------------------------------------------------------
__global__ void __launch_bounds__(THREADS) avg_kernel(
    const float* __restrict__ mel,
    float*       __restrict__ out)
{
    const int wid  = threadIdx.x >> 5;
    const int lane = threadIdx.x & 31;
    const int gp   = blockIdx.x * 4 + wid;   // global phoneme index
    const int b    = gp >> 10;               // / P
    const int p    = gp & (P - 1);           // % P

    // Wait for scan kernel's writes to be visible (PDL release).
    cudaGridDependencySynchronize();

    const int pk = g_seg[b * P + p];
    const int d  = pk & 15;
    const int st = pk >> 4;

    const float4* __restrict__ base =
        reinterpret_cast<const float4*>(mel + ((size_t)b * T + st) * D) + lane;

    float4 acc = make_float4(0.f, 0.f, 0.f, 0.f);
    #pragma unroll
    for (int f = 0; f < 8; ++f) {
        if (f < d) {
            float4 v = __ldcs(base + f * (D / 4));
            acc.x += v.x; acc.y += v.y; acc.z += v.z; acc.w += v.w;
        }
    }

    const float inv = (d > 0) ? (1.0f / (float)d) : 0.0f;
    acc.x *= inv; acc.y *= inv; acc.z *= inv; acc.w *= inv;

    __stcs(reinterpret_cast<float4*>(out + ((size_t)b * P + p) * D) + lane, acc);
}

extern "C" void kernel_launch(void* const* d_in, const int* in_sizes, int n_in,
                              void* d_out, int out_size) {
    const float* mel = (const float*)d_in[0];
    const int*   dur = (const int*)d_in[1];
    float*       out = (float*)d_out;

    scan_kernel<<<B, 256>>>(dur);

    cudaLaunchConfig_t cfg = {};
    cfg.gridDim  = dim3((B * P) / 4, 1, 1);
    cfg.blockDim = dim3(THREADS, 1, 1);
    cudaLaunchAttribute attrs[1];
    attrs[0].id = cudaLaunchAttributeProgrammaticStreamSerialization;
    attrs[0].val.programmaticStreamSerializationAllowed = 1;
    cfg.attrs    = attrs;
    cfg.numAttrs = 1;
    cudaLaunchKernelEx(&cfg, avg_kernel, mel, out);
}

// round 16
// speedup vs baseline: 1.1834x; 1.0477x over previous
#include <cuda_runtime.h>
#include <stdint.h>

// Problem shapes (fixed by the dataset)
#define B 32
#define T 8192
#define D 128
#define P 1024
#define THREADS 128   // 4 warps/block — measured optimum of the granularity axis

// Packed per-phoneme segment: (start << 4) | duration   (start < 8192, d <= 8)
__device__ int g_seg[B * P];

// ---------------------------------------------------------------------------
// Kernel 1: scan. 32 blocks x 256 threads; thread t owns durations [4t,4t+4)
// of its batch. shfl warp scan + cross-warp pass, writes packed segs (int4),
// then fence + early PDL trigger so the dependent gather releases at the
// last store instead of at kernel retirement.
// ---------------------------------------------------------------------------
__global__ void __launch_bounds__(256) scan_kernel(const int* __restrict__ dur) {
    __shared__ int s_wsum[8];
    const int b    = blockIdx.x;
    const int t    = threadIdx.x;
    const int lane = t & 31;
    const int wid  = t >> 5;

    const int4 dv = reinterpret_cast<const int4*>(dur + b * P)[t];
    const int tsum = dv.x + dv.y + dv.z + dv.w;

    int x = tsum;
    #pragma unroll
    for (int off = 1; off < 32; off <<= 1) {
        int y = __shfl_up_sync(0xFFFFFFFFu, x, off);
        if (lane >= off) x += y;
    }
    if (lane == 31) s_wsum[wid] = x;
    __syncthreads();

    if (wid == 0) {
        int s  = (lane < 8) ? s_wsum[lane] : 0;
        int tt = s;
        #pragma unroll
        for (int off = 1; off < 8; off <<= 1) {
            int y = __shfl_up_sync(0xFFFFFFFFu, tt, off);
            if (lane >= off) tt += y;
        }
        if (lane < 8) s_wsum[lane] = tt - s;
    }
    __syncthreads();

    int st = s_wsum[wid] + x - tsum;         // exclusive prefix before 4t
    int4 pk;
    pk.x = (st << 4) | dv.x;  st += dv.x;
    pk.y = (st << 4) | dv.y;  st += dv.y;
    pk.z = (st << 4) | dv.z;  st += dv.z;
    pk.w = (st << 4) | dv.w;
    reinterpret_cast<int4*>(g_seg + b * P)[t] = pk;

    // Make stores visible, then release PDL dependents early (before the
    // kernel's drain/retirement tail).
    __threadfence();
    cudaTriggerProgrammaticLaunchCompletion();
}

// ---------------------------------------------------------------------------
// Kernel 2: pure gather, PDL-launched. Grid 8192 x 128 threads (4 warps):
// one phoneme per warp. Nothing but index math before the PDL sync; one
// packed g_seg read after release, then 8 predicated __ldcs LDG.128 +
// 1 STG.128 per warp.
// ---------------------------------------------------------------------------
__global__ void __launch_bounds__(THREADS) avg_kernel(
    const float* __restrict__ mel,
    float*       __restrict__ out)
{
    const int wid  = threadIdx.x >> 5;
    const int lane = threadIdx.x & 31;
    const int gp   = blockIdx.x * 4 + wid;   // global phoneme index
    const int b    = gp >> 10;               // / P
    const int p    = gp & (P - 1);           // % P

    // Wait for scan kernel's fenced writes to be visible (PDL release).
    cudaGridDependencySynchronize();

    const int pk = g_seg[b * P + p];
    const int d  = pk & 15;
    const int st = pk >> 4;

    const float4* __restrict__ base =
        reinterpret_cast<const float4*>(mel + ((size_t)b * T + st) * D) + lane;

    float4 acc = make_float4(0.f, 0.f, 0.f, 0.f);
    #pragma unroll
    for (int f = 0; f < 8; ++f) {
        if (f < d) {
            float4 v = __ldcs(base + f * (D / 4));
            acc.x += v.x; acc.y += v.y; acc.z += v.z; acc.w += v.w;
        }
    }

    const float inv = (d > 0) ? (1.0f / (float)d) : 0.0f;
    acc.x *= inv; acc.y *= inv; acc.z *= inv; acc.w *= inv;

    __stcs(reinterpret_cast<float4*>(out + ((size_t)b * P + p) * D) + lane, acc);
}

extern "C" void kernel_launch(void* const* d_in, const int* in_sizes, int n_in,
                              void* d_out, int out_size) {
    const float* mel = (const float*)d_in[0];
    const int*   dur = (const int*)d_in[1];
    float*       out = (float*)d_out;

    scan_kernel<<<B, 256>>>(dur);

    cudaLaunchConfig_t cfg = {};
    cfg.gridDim  = dim3((B * P) / 4, 1, 1);
    cfg.blockDim = dim3(THREADS, 1, 1);
    cudaLaunchAttribute attrs[1];
    attrs[0].id = cudaLaunchAttributeProgrammaticStreamSerialization;
    attrs[0].val.programmaticStreamSerializationAllowed = 1;
    cfg.attrs    = attrs;
    cfg.numAttrs = 1;
    cudaLaunchKernelEx(&cfg, avg_kernel, mel, out);
}